// round 17
// baseline (speedup 1.0000x reference)
#include <cuda_runtime.h>
#include <cstdint>

// Problem constants
#define ROWS   65536        // B*n = 8192*8
#define NE     1024         // codebook size
#define ED     64           // codebook dim
#define CHUNK  128          // codebook entries staged per iteration
#define NCHUNK (NE / CHUNK) // 8
#define RPB    64           // rows per block
#define TR     8            // rows per warp (8 warps * 8 = 64)
#define TE     4            // entries per lane per chunk (CHUNK/32)

// Output layout (tuple flattened, all float32) — validated R1-R16
#define OFF_LOSS  0
#define OFF_L1    1
#define OFF_L2    2
#define OFF_ZQST  3
#define OFF_ZOUT  4194307
#define OFF_PERP  8388611
#define OFF_OH    8388612
#define OFF_IDX   75497476

__device__ int    g_hist[NE];
__device__ double g_loss;
__device__ float  g_wsum[NE];
__device__ int    g_counter;

__device__ __forceinline__ void ffma2(unsigned long long &acc,
                                      unsigned long long a,
                                      unsigned long long b) {
    asm("fma.rn.f32x2 %0, %1, %2, %0;" : "+l"(acc) : "l"(a), "l"(b));
}
__device__ __forceinline__ float2 unpack2(unsigned long long v) {
    float2 r;
    asm("mov.b64 {%0, %1}, %2;" : "=f"(r.x), "=f"(r.y) : "l"(v));
    return r;
}

// ---------------------------------------------------------------------------
// prep: per-entry ||w||^2 (per-warp math bit-identical to R16's vq_prep),
// zero histogram + loss accumulator + completion counter.
// 32 blocks x 1024 threads; warp w of block b owns entry b*32 + w.
// ---------------------------------------------------------------------------
__global__ void vq_prep(const float* __restrict__ w) {
    int lane = threadIdx.x & 31;
    int e = blockIdx.x * 32 + (threadIdx.x >> 5);
    const float* wr = w + e * ED;
    float a = wr[lane], b = wr[lane + 32];
    float s = a * a + b * b;
    #pragma unroll
    for (int o = 16; o; o >>= 1) s += __shfl_down_sync(0xffffffffu, s, o);
    if (lane == 0) {
        g_wsum[e] = s;
        g_hist[e] = 0;
        if (e == 0) { g_loss = 0.0; g_counter = 0; }
    }
}

// ---------------------------------------------------------------------------
// main kernel: fused distance-GEMM + row argmin + one-hot + z_q epilogue,
// PLUS last-block finalize (threadFenceReduction pattern). The mainloop,
// staging, swizzle, and epilogue are byte-identical to the 263/264-us R4/R16
// source; only the post-epilogue tail is new.
// Scores: (||z||^2 + ||w||^2) - 2*dot, fp32, dp-ascending (= R4).
// ---------------------------------------------------------------------------
__global__ __launch_bounds__(256) void vq_argmin(
    const float* __restrict__ z, const float* __restrict__ w,
    float* __restrict__ out)
{
    __shared__ float  zs[RPB * ED];       // 16384 B: z tile (row-major)
    __shared__ float2 wp[32 * CHUNK];     // 32768 B: w chunk [dpair][entry] swizzled

    const int tid = threadIdx.x, lane = tid & 31, warp = tid >> 5;
    const int rowBase = blockIdx.x * RPB;
    const int myRow0 = warp * TR;

    // stage z tile (coalesced float4)
    {
        const float4* zg = (const float4*)(z + (size_t)rowBase * ED);
        float4* zt = (float4*)zs;
        #pragma unroll
        for (int i = tid; i < RPB * ED / 4; i += 256) zt[i] = zg[i];
    }
    __syncthreads();

    // per-warp zsum: lane r (<8) owns row myRow0+r, sequential order (= R1)
    float myzsum = 0.f;
    if (lane < TR) {
        const float* zr = zs + (myRow0 + lane) * ED;
        #pragma unroll
        for (int d = 0; d < ED; d++) myzsum += zr[d] * zr[d];
    }

    float best[TR]; int bidx[TR];
    #pragma unroll
    for (int r = 0; r < TR; r++) { best[r] = 3.402823e38f; bidx[r] = 0x7fffffff; }

    const float2* zs2 = (const float2*)zs;
    float4* ohp = (float4*)(out + OFF_OH + (size_t)rowBase * NE);
    const float4 zero4 = make_float4(0.f, 0.f, 0.f, 0.f);

    for (int c = 0; c < NE; c += CHUNK) {
        __syncthreads();   // protect wp reuse
        // stage w chunk as [dpair][entry] with xor-swizzle (conflict-free LDS)
        {
            const float2* wg = (const float2*)(w + (size_t)c * ED);
            #pragma unroll
            for (int i = tid; i < CHUNK * 32; i += 256) {
                int e = i >> 5, dp = i & 31;
                int col = (e & ~31) | ((e & 31) ^ dp);
                wp[dp * CHUNK + col] = wg[i];
            }
        }
        __syncthreads();

        // fire-and-forget: zero 1/NCHUNK of this block's one-hot slice
        {
            int it = c / CHUNK;                    // 0..7
            #pragma unroll
            for (int k = 0; k < (RPB * NE / 4) / (NCHUNK * 256); k++)
                ohp[it * (RPB * NE / 4 / NCHUNK) + k * 256 + tid] = zero4;
        }

        unsigned long long acc[TR][TE];
        #pragma unroll
        for (int r = 0; r < TR; r++)
            #pragma unroll
            for (int j = 0; j < TE; j++) acc[r][j] = 0ull;

        #pragma unroll 8
        for (int dp = 0; dp < 32; dp++) {
            unsigned long long zv[TR], wv[TE];
            #pragma unroll
            for (int r = 0; r < TR; r++)
                zv[r] = *(const unsigned long long*)&zs2[(myRow0 + r) * 32 + dp];
            #pragma unroll
            for (int j = 0; j < TE; j++) {
                int col = (j << 5) | (lane ^ dp);
                wv[j] = *(const unsigned long long*)&wp[dp * CHUNK + col];
            }
            #pragma unroll
            for (int r = 0; r < TR; r++)
                #pragma unroll
                for (int j = 0; j < TE; j++)
                    ffma2(acc[r][j], zv[r], wv[j]);
        }

        #pragma unroll
        for (int r = 0; r < TR; r++) {
            float zsr = __shfl_sync(0xffffffffu, myzsum, r);
            #pragma unroll
            for (int j = 0; j < TE; j++) {
                float2 a = unpack2(acc[r][j]);
                float dot = a.x + a.y;
                int e = c + (j << 5) + lane;
                float t = zsr + g_wsum[e];
                float s = t - 2.0f * dot;      // matches reference fp32 ordering
                if (s < best[r] || (s == best[r] && e < bidx[r])) {
                    best[r] = s; bidx[r] = e;
                }
            }
        }
    }

    __syncthreads();   // fence: all one-hot zeros precede the 1.0 stores below

    // per-row warp reduction + epilogue
    double dacc = 0.0;
    #pragma unroll
    for (int r = 0; r < TR; r++) {
        float v = best[r]; int id = bidx[r];
        #pragma unroll
        for (int o = 16; o; o >>= 1) {
            float v2 = __shfl_down_sync(0xffffffffu, v, o);
            int   i2 = __shfl_down_sync(0xffffffffu, id, o);
            if (v2 < v || (v2 == v && i2 < id)) { v = v2; id = i2; }
        }
        id = __shfl_sync(0xffffffffu, id, 0);

        int grow = rowBase + myRow0 + r;
        const float* wrow = w + (size_t)id * ED;
        float dsq = 0.f;
        #pragma unroll
        for (int d = lane; d < ED; d += 32) {
            float zq = wrow[d];                  // z_q = exact codebook row
            float zr = zs[(myRow0 + r) * ED + d];
            float df = zq - zr;
            float st = zr + df;                  // straight-through fp32 replay
            out[OFF_ZQST + (size_t)grow * ED + d] = st;
            out[OFF_ZOUT + (size_t)grow * ED + d] = st;
            dsq += df * df;
        }
        #pragma unroll
        for (int o = 16; o; o >>= 1) dsq += __shfl_down_sync(0xffffffffu, dsq, o);
        if (lane == 0) {
            atomicAdd(&g_hist[id], 1);
            out[OFF_IDX + grow] = (float)id;
            out[OFF_OH + (size_t)grow * NE + id] = 1.0f;   // after fenced zeros
            dacc += (double)dsq;
        }
    }
    if (lane == 0 && dacc != 0.0) atomicAdd(&g_loss, dacc);

    // ---- last-block finalize (threadFenceReduction pattern) ----
    __threadfence();                      // publish g_hist / g_loss
    if (tid == 0) {
        int prev = atomicAdd(&g_counter, 1);
        zs[256] = (prev == (int)gridDim.x - 1) ? 1.0f : 0.0f;   // reuse dead zs
    }
    __syncthreads();
    if (zs[256] != 0.0f) {
        float* red = zs;                  // reuse dead z tile as scratch
        float ps = 0.f;
        #pragma unroll
        for (int k = 0; k < NE / 256; k++) {
            float p = (float)g_hist[tid * (NE / 256) + k] / 65536.0f;
            ps += p * logf(p + 1e-10f);
        }
        __syncthreads();                  // zs[256] flag consumed by all
        red[tid] = ps;
        __syncthreads();
        #pragma unroll
        for (int s = 128; s; s >>= 1) {
            if (tid < s) red[tid] += red[tid + s];
            __syncthreads();
        }
        if (tid == 0) {
            out[OFF_PERP] = expf(-red[0]);
            float l1 = (float)(g_loss / 4194304.0);
            out[OFF_L1] = l1;
            out[OFF_L2] = l1;                 // loss2 == loss1 numerically
            out[OFF_LOSS] = l1 + 0.25f * l1;  // GAMMA*l1 + BETA*l2
        }
    }
}

// ---------------------------------------------------------------------------
extern "C" void kernel_launch(void* const* d_in, const int* in_sizes, int n_in,
                              void* d_out, int out_size)
{
    const float* z = (const float*)d_in[0];   // (8192, 512)
    const float* w = (const float*)d_in[1];   // (1024, 64)
    float* out = (float*)d_out;

    vq_prep<<<32, 1024>>>(w);
    vq_argmin<<<ROWS / RPB, 256>>>(z, w, out);
}